// round 2
// baseline (speedup 1.0000x reference)
#include <cuda_runtime.h>
#include <cuda_bf16.h>

#define B_ 4
#define T_ 2048
#define H_ 16
#define D_ 128
#define HD 2048        // H_*D_
#define S_ 16          // steps per chunk
#define NC (T_/S_)     // 128 chunks

typedef unsigned long long u64;

__device__ __forceinline__ u64 pk2(float x, float y) {
    u64 r; asm("mov.b64 %0,{%1,%2};" : "=l"(r) : "f"(x), "f"(y)); return r;
}
__device__ __forceinline__ float2 up2(u64 a) {
    float2 r; asm("mov.b64 {%0,%1},%2;" : "=f"(r.x), "=f"(r.y) : "l"(a)); return r;
}
__device__ __forceinline__ u64 mul2(u64 a, u64 b) {
    u64 d; asm("mul.rn.f32x2 %0,%1,%2;" : "=l"(d) : "l"(a), "l"(b)); return d;
}
__device__ __forceinline__ u64 fma2(u64 a, u64 b, u64 c) {
    u64 d; asm("fma.rn.f32x2 %0,%1,%2,%3;" : "=l"(d) : "l"(a), "l"(b), "l"(c)); return d;
}
__device__ __forceinline__ u64 max2c(u64 a, float c) {
    float2 t = up2(a);
    t.x = fmaxf(t.x, c); t.y = fmaxf(t.y, c);
    return pk2(t.x, t.y);
}

// Row-data smem layout per t: 8 blocks of (16 floats + 4 pad) = 160 floats (640B).
// Block-base banks: r*20 mod 32 = {0,20,8,28,16,4,24,12} -> conflict-free LDS.128.
__global__ __launch_bounds__(512, 1) void delta_kernel(
    const float* __restrict__ q, const float* __restrict__ k,
    const float* __restrict__ v, const float* __restrict__ f,
    const float* __restrict__ g, float* __restrict__ out)
{
    __shared__ float fsm[S_ * 160];
    __shared__ float ksm[S_ * 160];   // holds kg = k*g
    __shared__ float qsm[S_ * 160];
    __shared__ float vgsm[S_ * 64];   // vg = v*g for this CTA's 64 columns

    const int tid  = threadIdx.x;
    const int w    = tid >> 5, lane = tid & 31;
    const int r    = lane >> 2;          // 8 row-groups of 16 rows
    const int c    = lane & 3;           // 4 columns per warp
    const int colbase = blockIdx.x * 64;
    const long base0  = (long)blockIdx.z * T_ * HD + (long)blockIdx.y * D_;

    // staging roles
    const int  s_s = tid >> 5, s_rb = tid & 31;   // rows: (step, 4-row block)
    const int  c_s = tid >> 4, c_cb = tid & 15;   // cols: (step, 4-col block)
    const bool colth = (tid < 256);
    const long growb = base0 + (long)s_s * HD + s_rb * 4;
    const long gcolb = base0 + (long)c_s * HD + colbase + c_cb * 4;

    // prefetch chunk 0 into registers
    float4 pq  = *(const float4*)(q + growb);
    float4 pk_ = *(const float4*)(k + growb);
    float4 pg  = *(const float4*)(g + growb);
    float4 pf  = *(const float4*)(f + growb);
    float4 cv, cg;
    if (colth) { cv = *(const float4*)(v + gcolb); cg = *(const float4*)(g + gcolb); }

    // state: 16 rows x 1 col as 8 packed f32x2
    u64 M[8];
#pragma unroll
    for (int p = 0; p < 8; p++) M[p] = 0ull;

    const int rbidx  = s_s * 160 + (s_rb >> 2) * 20 + (s_rb & 3) * 4;  // staging write idx
    const int rl     = r * 20;                                          // compute read base
    const int cj     = colbase + w * 4 + c;                             // my column
    const int fcidx  = (cj >> 4) * 20 + (cj & 15);
    const int vcidx  = w * 4 + c;
    float* outp = out + base0 + cj;

    for (int ch = 0; ch < NC; ch++) {
        __syncthreads();                       // smem free (prev chunk consumed)
        // ---- stage prefetched regs -> smem ----
        {
            float4 kg;
            kg.x = pk_.x * pg.x; kg.y = pk_.y * pg.y;
            kg.z = pk_.z * pg.z; kg.w = pk_.w * pg.w;
            *(float4*)(fsm + rbidx) = pf;
            *(float4*)(ksm + rbidx) = kg;
            *(float4*)(qsm + rbidx) = pq;
            if (colth) {
                float4 vg;
                vg.x = cv.x * cg.x; vg.y = cv.y * cg.y;
                vg.z = cv.z * cg.z; vg.w = cv.w * cg.w;
                *(float4*)(vgsm + c_s * 64 + c_cb * 4) = vg;
            }
        }
        __syncthreads();
        // ---- prefetch next chunk (latency overlaps compute) ----
        if (ch + 1 < NC) {
            long off = (long)(ch + 1) * S_ * HD;
            pq  = *(const float4*)(q + growb + off);
            pk_ = *(const float4*)(k + growb + off);
            pg  = *(const float4*)(g + growb + off);
            pf  = *(const float4*)(f + growb + off);
            if (colth) {
                cv = *(const float4*)(v + gcolb + off);
                cg = *(const float4*)(g + gcolb + off);
            }
        }
        // ---- compute 16 steps ----
        const int tglob = ch * S_;
#pragma unroll
        for (int s = 0; s < S_; s++) {
            const float* fb = fsm + s * 160 + rl;
            const float* kb = ksm + s * 160 + rl;
            const float* qb = qsm + s * 160 + rl;
            const float fc  = fsm[s * 160 + fcidx];
            const float vgc = vgsm[s * 64 + vcidx];
            const u64 fj = pk2(fc, fc);
            const u64 vj = pk2(vgc, vgc);
            u64 o2 = 0ull;
#pragma unroll
            for (int l = 0; l < 4; l++) {
                float4 f4 = *(const float4*)(fb + l * 4);
                float4 k4 = *(const float4*)(kb + l * 4);
                float4 q4 = *(const float4*)(qb + l * 4);
                u64 fo, wv;
                fo = max2c(mul2(pk2(f4.x, f4.y), fj), 0.8f);
                wv = mul2(pk2(k4.x, k4.y), vj);
                M[l * 2] = fma2(M[l * 2], fo, wv);
                o2 = fma2(pk2(q4.x, q4.y), M[l * 2], o2);
                fo = max2c(mul2(pk2(f4.z, f4.w), fj), 0.8f);
                wv = mul2(pk2(k4.z, k4.w), vj);
                M[l * 2 + 1] = fma2(M[l * 2 + 1], fo, wv);
                o2 = fma2(pk2(q4.z, q4.w), M[l * 2 + 1], o2);
            }
            float2 oo = up2(o2);
            float osum = oo.x + oo.y;
            osum += __shfl_xor_sync(0xffffffffu, osum, 4);
            osum += __shfl_xor_sync(0xffffffffu, osum, 8);
            osum += __shfl_xor_sync(0xffffffffu, osum, 16);
            if (lane < 4) outp[(long)(tglob + s) * HD] = osum;
        }
    }
}

extern "C" void kernel_launch(void* const* d_in, const int* in_sizes, int n_in,
                              void* d_out, int out_size) {
    const float* q = (const float*)d_in[0];
    const float* k = (const float*)d_in[1];
    const float* v = (const float*)d_in[2];
    const float* f = (const float*)d_in[3];
    const float* g = (const float*)d_in[4];
    dim3 grid(2, H_, B_);
    delta_kernel<<<grid, 512>>>(q, k, v, f, g, (float*)d_out);
}